// round 15
// baseline (speedup 1.0000x reference)
#include <cuda_runtime.h>
#include <cuda_bf16.h>
#include <math.h>
#include <stdint.h>

#define B_ 2
#define S_ 2048
#define D_ 1024
#define H_ 16
#define DK_ 64
#define TD_ 3072          // 3*D
#define MROWS_ 4096       // B*S
#define QUARTER_ 16
#define GK_ 1024          // K dim of both projections

// ---------------------------------------------------------------------------
// Scratch (device globals — no allocation allowed)
// ---------------------------------------------------------------------------
__device__ float g_qkv[B_ * S_ * TD_];   // [B,S,3D] fp32 (QKV GEMM output)
__device__ float g_cos[S_ * QUARTER_];
__device__ float g_sin[S_ * QUARTER_];
// bf16 split-precision operand buffers for projections
__device__ __nv_bfloat16 g_xh[MROWS_ * D_],  g_xl[MROWS_ * D_];
__device__ __nv_bfloat16 g_wqh[TD_ * D_],    g_wql[TD_ * D_];
__device__ __nv_bfloat16 g_woh[D_ * D_],     g_wol[D_ * D_];
__device__ __nv_bfloat16 g_ath[MROWS_ * D_], g_atl[MROWS_ * D_];
// attention operands, split hi/lo. q/k: [b,h,s,dk]. v: TRANSPOSED [b,h,dk,s].
#define QKVN_ (B_ * H_ * S_ * DK_)
__device__ __nv_bfloat16 g_qh[QKVN_], g_ql[QKVN_];
__device__ __nv_bfloat16 g_kh[QKVN_], g_kl[QKVN_];
__device__ __nv_bfloat16 g_vth[QKVN_], g_vtl[QKVN_];

// ---------------------------------------------------------------------------
// small helpers
// ---------------------------------------------------------------------------
__device__ __forceinline__ uint32_t pk2(float a, float b) {
    __nv_bfloat162 t = __floats2bfloat162_rn(a, b);
    return *reinterpret_cast<uint32_t*>(&t);
}
__device__ __forceinline__ float lo_of(float v) {
    return v - __bfloat162float(__float2bfloat16(v));
}
__device__ __forceinline__ uint32_t sm_u32(const void* p) {
    return (uint32_t)__cvta_generic_to_shared(p);
}
__device__ __forceinline__ void cp16(uint32_t dst_sm, const void* src) {
    asm volatile("cp.async.cg.shared.global [%0], [%1], 16;"
                 :: "r"(dst_sm), "l"(src));
}
#define CP_COMMIT() asm volatile("cp.async.commit_group;" ::: "memory")
#define CP_WAIT1()  asm volatile("cp.async.wait_group 1;" ::: "memory")
#define CP_WAIT0()  asm volatile("cp.async.wait_group 0;" ::: "memory")

#define MMA16816(d, a, b) \
    asm volatile( \
        "mma.sync.aligned.m16n8k16.row.col.f32.bf16.bf16.f32 " \
        "{%0,%1,%2,%3}, {%4,%5,%6,%7}, {%8,%9}, {%0,%1,%2,%3};" \
        : "+f"((d)[0]), "+f"((d)[1]), "+f"((d)[2]), "+f"((d)[3]) \
        : "r"((a)[0]), "r"((a)[1]), "r"((a)[2]), "r"((a)[3]), \
          "r"((b)[0]), "r"((b)[1]))

#define LDSM4(r0, r1, r2, r3, addr) \
    asm volatile( \
        "ldmatrix.sync.aligned.m8n8.x4.shared.b16 {%0,%1,%2,%3}, [%4];" \
        : "=r"(r0), "=r"(r1), "=r"(r2), "=r"(r3) : "r"(addr))

// ---------------------------------------------------------------------------
// RoPE tables
// ---------------------------------------------------------------------------
__global__ void rope_table_k() {
    int i = blockIdx.x * blockDim.x + threadIdx.x;
    if (i >= S_ * QUARTER_) return;
    int s = i / QUARTER_;
    int j = i % QUARTER_;
    double ang = pow(1.0e-4, (double)j / (double)(QUARTER_ - 1));
    double th = (double)s * ang;
    g_cos[i] = (float)cos(th);
    g_sin[i] = (float)sin(th);
}

// ---------------------------------------------------------------------------
// fp32 -> (bf16 hi, bf16 lo) splitter
// ---------------------------------------------------------------------------
__global__ __launch_bounds__(256)
void split_k(const float* __restrict__ src, __nv_bfloat16* __restrict__ hi,
             __nv_bfloat16* __restrict__ lo, int n4) {
    int i = blockIdx.x * blockDim.x + threadIdx.x;
    if (i >= n4) return;
    float4 v = ((const float4*)src)[i];
    ((uint32_t*)hi)[2 * i + 0] = pk2(v.x, v.y);
    ((uint32_t*)hi)[2 * i + 1] = pk2(v.z, v.w);
    ((uint32_t*)lo)[2 * i + 0] = pk2(lo_of(v.x), lo_of(v.y));
    ((uint32_t*)lo)[2 * i + 1] = pk2(lo_of(v.z), lo_of(v.w));
}

// ---------------------------------------------------------------------------
// prep: RoPE + split q,k into [b,h,s,dk] (V handled by vtrans_k)
// ---------------------------------------------------------------------------
__device__ __forceinline__ void wr4(__nv_bfloat16* H, __nv_bfloat16* L,
                                    const float* v) {
    uint2 hh, ll;
    hh.x = pk2(v[0], v[1]); hh.y = pk2(v[2], v[3]);
    ll.x = pk2(lo_of(v[0]), lo_of(v[1]));
    ll.y = pk2(lo_of(v[2]), lo_of(v[3]));
    *(uint2*)H = hh;
    *(uint2*)L = ll;
}

__global__ __launch_bounds__(256)
void prep_k() {
    int idx = blockIdx.x * blockDim.x + threadIdx.x;
    if (idx >= B_ * H_ * S_ * 8) return;
    int t = idx & 7;
    int r = idx >> 3;
    int s = r & (S_ - 1); r >>= 11;
    int h = r & (H_ - 1);
    int b = r >> 4;
    int jj = (t < 4) ? (t << 2) : (16 + ((t - 4) << 2));
    size_t src = (size_t)(b * S_ + s) * TD_ + h * DK_;
    size_t dst = ((size_t)(b * H_ + h) * S_ + s) * DK_;

    float c[4], sn[4];
    bool dorope = jj < 16;
    if (dorope) {
        #pragma unroll
        for (int i = 0; i < 4; i++) {
            c[i]  = g_cos[s * QUARTER_ + jj + i];
            sn[i] = g_sin[s * QUARTER_ + jj + i];
        }
    }
    #pragma unroll
    for (int part = 0; part < 2; part++) {
        float4 x1 = *(const float4*)&g_qkv[src + part * D_ + jj];
        float4 x2 = *(const float4*)&g_qkv[src + part * D_ + jj + 32];
        float a[4] = {x1.x, x1.y, x1.z, x1.w};
        float bb[4] = {x2.x, x2.y, x2.z, x2.w};
        if (dorope) {
            #pragma unroll
            for (int i = 0; i < 4; i++) {
                float na = a[i] * c[i] - bb[i] * sn[i];
                float nb = a[i] * sn[i] + bb[i] * c[i];
                a[i] = na; bb[i] = nb;
            }
        }
        __nv_bfloat16* Hh = part ? g_kh : g_qh;
        __nv_bfloat16* Ll = part ? g_kl : g_ql;
        wr4(Hh + dst + jj, Ll + dst + jj, a);
        wr4(Hh + dst + jj + 32, Ll + dst + jj + 32, bb);
    }
}

// ---------------------------------------------------------------------------
// vtrans: V slice of g_qkv [b,s,2D+h*64+d] -> transposed split bf16 [b,h,d,s]
// One block per (64-s-tile, h, b); 64x64 tile through smem.
// ---------------------------------------------------------------------------
__global__ __launch_bounds__(256)
void vtrans_k() {
    __shared__ float tile[64 * 65];
    int b = blockIdx.z, h = blockIdx.y;
    int s0 = blockIdx.x << 6;
    int tid = threadIdx.x;
    int row = tid >> 2;          // 0..63
    int quar = tid & 3;          // 0..3

    // read rows (s fixed, d contiguous): 16 fp32 per thread
    {
        const float* src = g_qkv + (size_t)(b * S_ + s0 + row) * TD_ +
                           2 * D_ + h * DK_ + quar * 16;
        #pragma unroll
        for (int u = 0; u < 4; u++) {
            float4 v = *(const float4*)(src + u * 4);
            tile[(quar * 16 + u * 4 + 0) * 65 + row] = v.x;
            tile[(quar * 16 + u * 4 + 1) * 65 + row] = v.y;
            tile[(quar * 16 + u * 4 + 2) * 65 + row] = v.z;
            tile[(quar * 16 + u * 4 + 3) * 65 + row] = v.w;
        }
    }
    __syncthreads();
    // write rows (d fixed, s contiguous): 16 values per thread
    {
        int d = row;
        size_t dst = ((size_t)(b * H_ + h) * DK_ + d) * S_ + s0 + quar * 16;
        #pragma unroll
        for (int u = 0; u < 4; u++) {
            float v0 = tile[d * 65 + quar * 16 + u * 4 + 0];
            float v1 = tile[d * 65 + quar * 16 + u * 4 + 1];
            float v2 = tile[d * 65 + quar * 16 + u * 4 + 2];
            float v3 = tile[d * 65 + quar * 16 + u * 4 + 3];
            uint2 hh, ll;
            hh.x = pk2(v0, v1); hh.y = pk2(v2, v3);
            ll.x = pk2(lo_of(v0), lo_of(v1)); ll.y = pk2(lo_of(v2), lo_of(v3));
            *(uint2*)&g_vth[dst + u * 4] = hh;
            *(uint2*)&g_vtl[dst + u * 4] = ll;
        }
    }
}

// ---------------------------------------------------------------------------
// mma.sync split-bf16 GEMM, cp.async 2-stage pipeline + ldmatrix.
// CTA 128x128, BK=32, 8 warps (warp tile 64x32), fp32 accum.
// ---------------------------------------------------------------------------
#define BK_ 32
#define ASTR_ 40
#define TILE_ELEMS_ (128 * ASTR_)
#define TILE_B_ (TILE_ELEMS_ * 2)          // bytes per operand tile
#define GSTAGE_B_ (4 * TILE_B_)            // 40960 bytes per stage
#define GEMM_SMEM_ (2 * GSTAGE_B_)         // 81920

__device__ __forceinline__ void stage_cp(
    uint32_t stage_u,
    const __nv_bfloat16* __restrict__ Ah, const __nv_bfloat16* __restrict__ Al,
    const __nv_bfloat16* __restrict__ Bh, const __nv_bfloat16* __restrict__ Bl,
    int bm, int bn, int kc, int tid) {
    #pragma unroll
    for (int u = 0; u < 8; u++) {
        int id = tid + (u << 8);
        int tile = id >> 9;
        int rem = id & 511;
        int row = rem >> 2;
        int seg = rem & 3;
        const __nv_bfloat16* src;
        if (tile == 0)      src = Ah + (size_t)(bm + row) * GK_;
        else if (tile == 1) src = Al + (size_t)(bm + row) * GK_;
        else if (tile == 2) src = Bh + (size_t)(bn + row) * GK_;
        else                src = Bl + (size_t)(bn + row) * GK_;
        cp16(stage_u + (tile * TILE_ELEMS_ + row * ASTR_ + seg * 8) * 2,
             src + kc + seg * 8);
    }
}

__global__ __launch_bounds__(256, 1)
void gemm_mma(const __nv_bfloat16* __restrict__ Ah, const __nv_bfloat16* __restrict__ Al,
              const __nv_bfloat16* __restrict__ Bh, const __nv_bfloat16* __restrict__ Bl,
              float* __restrict__ C, int N) {
    extern __shared__ __nv_bfloat16 smg[];
    uint32_t base_u = sm_u32(smg);
    int tid = threadIdx.x;
    int lane = tid & 31, wid = tid >> 5;
    int warp_m = wid & 1;
    int warp_n = wid >> 1;
    int bm = blockIdx.y << 7, bn = blockIdx.x << 7;

    int g = lane >> 2;
    int tg2 = (lane & 3) << 1;

    int arow = ((lane >> 3) & 1) * 8 + (lane & 7);
    int acol = (lane >> 4) * 8;
    int brow = (lane >> 4) * 8 + (lane & 7);
    int bcol = ((lane >> 3) & 1) * 8;
    uint32_t aAddr0 = base_u + ((warp_m * 64 + arow) * ASTR_ + acol) * 2;
    uint32_t bAddr0 = base_u + 2 * TILE_B_ +
                      ((warp_n * 32 + brow) * ASTR_ + bcol) * 2;

    float acc[4][4][4];
    #pragma unroll
    for (int mt = 0; mt < 4; mt++)
        #pragma unroll
        for (int nt = 0; nt < 4; nt++)
            #pragma unroll
            for (int r = 0; r < 4; r++) acc[mt][nt][r] = 0.f;

    stage_cp(base_u, Ah, Al, Bh, Bl, bm, bn, 0, tid);
    CP_COMMIT();

    const int nchunks = GK_ / BK_;
    for (int c = 0; c < nchunks; c++) {
        if (c + 1 < nchunks) {
            stage_cp(base_u + ((c + 1) & 1) * GSTAGE_B_,
                     Ah, Al, Bh, Bl, bm, bn, (c + 1) * BK_, tid);
            CP_COMMIT();
            CP_WAIT1();
        } else {
            CP_WAIT0();
        }
        __syncthreads();
        uint32_t soff = (c & 1) * GSTAGE_B_;

        #pragma unroll
        for (int kk = 0; kk < 2; kk++) {
            uint32_t koff = soff + kk * 16 * 2;
            uint32_t ahf[4][4], alf[4][4], bhf[4][2], blf[4][2];
            #pragma unroll
            for (int mt = 0; mt < 4; mt++) {
                uint32_t a = aAddr0 + mt * (16 * ASTR_ * 2) + koff;
                LDSM4(ahf[mt][0], ahf[mt][1], ahf[mt][2], ahf[mt][3], a);
                LDSM4(alf[mt][0], alf[mt][1], alf[mt][2], alf[mt][3],
                      a + TILE_B_);
            }
            #pragma unroll
            for (int p = 0; p < 2; p++) {
                uint32_t bA = bAddr0 + p * (16 * ASTR_ * 2) + koff;
                LDSM4(bhf[2 * p][0], bhf[2 * p][1],
                      bhf[2 * p + 1][0], bhf[2 * p + 1][1], bA);
                LDSM4(blf[2 * p][0], blf[2 * p][1],
                      blf[2 * p + 1][0], blf[2 * p + 1][1], bA + TILE_B_);
            }
            #pragma unroll
            for (int mt = 0; mt < 4; mt++)
                #pragma unroll
                for (int nt = 0; nt < 4; nt++) {
                    MMA16816(acc[mt][nt], ahf[mt], bhf[nt]);
                    MMA16816(acc[mt][nt], ahf[mt], blf[nt]);
                    MMA16816(acc[mt][nt], alf[mt], bhf[nt]);
                }
        }
        __syncthreads();
    }

    #pragma unroll
    for (int mt = 0; mt < 4; mt++) {
        int m = bm + warp_m * 64 + mt * 16 + g;
        #pragma unroll
        for (int nt = 0; nt < 4; nt++) {
            int n = bn + warp_n * 32 + nt * 8 + tg2;
            *(float2*)&C[(size_t)m * N + n] =
                make_float2(acc[mt][nt][0], acc[mt][nt][1]);
            *(float2*)&C[(size_t)(m + 8) * N + n] =
                make_float2(acc[mt][nt][2], acc[mt][nt][3]);
        }
    }
}

// ---------------------------------------------------------------------------
// Flash attention: mma.sync split-bf16 + ldmatrix + cp.async 2-stage KV ring.
// CTA: 128 q-rows for one (b,h). 8 warps, warp w owns rows 16w..16w+15.
// V is pre-transposed in gmem, so both K and V tiles are straight copies.
// ---------------------------------------------------------------------------
#define PADT_ 72
#define KVSTAGE_E_ (4 * 64 * PADT_)             // elems per stage
#define KVSTAGE_B_ (KVSTAGE_E_ * 2)             // 36864 bytes
#define ATT_SMEM_ ((2 * 128 * PADT_ + 2 * KVSTAGE_E_) * 2)  // 110592

__global__ __launch_bounds__(256)
void attn_mma() {
    extern __shared__ __nv_bfloat16 smb[];
    __nv_bfloat16* sQh = smb;
    __nv_bfloat16* sQl = sQh + 128 * PADT_;
    uint32_t stage0_u = sm_u32(sQl + 128 * PADT_);

    int tid = threadIdx.x;
    int lane = tid & 31, w = tid >> 5;
    int g = lane >> 2;
    int q2 = (lane & 3) << 1;
    int b = blockIdx.z, h = blockIdx.y;
    int qt = (int)gridDim.x - 1 - (int)blockIdx.x;   // heavy tiles first
    int q0 = qt << 7;
    size_t base = ((size_t)(b * H_ + h)) * S_ * DK_;
    size_t baseT = ((size_t)(b * H_ + h)) * DK_ * S_;   // transposed V

    // ldmatrix per-lane components for B-style frags (K and V)
    int brow = (lane >> 4) * 8 + (lane & 7);
    int bcol = ((lane >> 3) & 1) * 8;
    uint32_t bfragoff = (brow * PADT_ + bcol) * 2;

    // ---- load Q tile (128 x 64) hi/lo into smem ----
    {
        int row = tid >> 1;
        int half = (tid & 1) << 2;
        const uint4* gh = (const uint4*)(g_qh + base + (size_t)(q0 + row) * DK_);
        const uint4* gl = (const uint4*)(g_ql + base + (size_t)(q0 + row) * DK_);
        uint4* dh = (uint4*)(sQh + row * PADT_);
        uint4* dl = (uint4*)(sQl + row * PADT_);
        #pragma unroll
        for (int u = 0; u < 4; u++) {
            dh[half + u] = gh[half + u];
            dl[half + u] = gl[half + u];
        }
    }

    int nkt = 2 * (qt + 1);
    // issue KV tile 0 while Q smem settles
    {
        #pragma unroll
        for (int u = 0; u < 8; u++) {
            int id = tid + (u << 8);
            int tile = id >> 9;      // 0:Kh 1:Kl 2:Vh 3:Vl
            int rem = id & 511;
            int row = rem >> 3;      // 0..63 (key row for K, d row for V)
            int seg = rem & 7;       // 16B segment
            const __nv_bfloat16* src;
            if (tile == 0)      src = g_kh + base + (size_t)row * DK_ + seg * 8;
            else if (tile == 1) src = g_kl + base + (size_t)row * DK_ + seg * 8;
            else if (tile == 2) src = g_vth + baseT + (size_t)row * S_ + seg * 8;
            else                src = g_vtl + baseT + (size_t)row * S_ + seg * 8;
            cp16(stage0_u + (tile * 64 * PADT_ + row * PADT_ + seg * 8) * 2, src);
        }
        CP_COMMIT();
    }
    __syncthreads();   // Q ready for ldmatrix

    // ---- hoist Q fragments ----
    uint32_t qfh[4][4], qfl[4][4];
    {
        int arow = ((lane >> 3) & 1) * 8 + (lane & 7);
        int acol = (lane >> 4) * 8;
        uint32_t qh_u = sm_u32(sQh) + ((w * 16 + arow) * PADT_ + acol) * 2;
        uint32_t ql_u = sm_u32(sQl) + ((w * 16 + arow) * PADT_ + acol) * 2;
        #pragma unroll
        for (int ks = 0; ks < 4; ks++) {
            LDSM4(qfh[ks][0], qfh[ks][1], qfh[ks][2], qfh[ks][3],
                  qh_u + ks * 32);
            LDSM4(qfl[ks][0], qfl[ks][1], qfl[ks][2], qfl[ks][3],
                  ql_u + ks * 32);
        }
    }

    float oacc[8][4];
    #pragma unroll
    for (int nt = 0; nt < 8; nt++)
        #pragma unroll
        for (int r = 0; r < 4; r++) oacc[nt][r] = 0.f;
    float m0 = -1e30f, m1 = -1e30f, l0 = 0.f, l1 = 0.f;
    int row0 = q0 + w * 16 + g, row1 = row0 + 8;

    for (int kt = 0; kt < nkt; kt++) {
        int k0 = kt << 6;
        // issue next tile into the other stage
        if (kt + 1 < nkt) {
            int k1 = (kt + 1) << 6;
            uint32_t st_u = stage0_u + ((kt + 1) & 1) * KVSTAGE_B_;
            #pragma unroll
            for (int u = 0; u < 8; u++) {
                int id = tid + (u << 8);
                int tile = id >> 9;
                int rem = id & 511;
                int row = rem >> 3;
                int seg = rem & 7;
                const __nv_bfloat16* src;
                if (tile == 0)
                    src = g_kh + base + (size_t)(k1 + row) * DK_ + seg * 8;
                else if (tile == 1)
                    src = g_kl + base + (size_t)(k1 + row) * DK_ + seg * 8;
                else if (tile == 2)
                    src = g_vth + baseT + (size_t)row * S_ + k1 + seg * 8;
                else
                    src = g_vtl + baseT + (size_t)row * S_ + k1 + seg * 8;
                cp16(st_u + (tile * 64 * PADT_ + row * PADT_ + seg * 8) * 2, src);
            }
            CP_COMMIT();
            CP_WAIT1();
        } else {
            CP_WAIT0();
        }
        __syncthreads();

        uint32_t st_u = stage0_u + (kt & 1) * KVSTAGE_B_;
        uint32_t kA0 = st_u + bfragoff;                         // Kh
        uint32_t kA0l = st_u + 64 * PADT_ * 2 + bfragoff;       // Kl
        uint32_t vA0 = st_u + 2 * 64 * PADT_ * 2 + bfragoff;    // Vh
        uint32_t vA0l = st_u + 3 * 64 * PADT_ * 2 + bfragoff;   // Vl

        // ---- S = Q K^T (3-term split) ----
        float sacc[8][4];
        #pragma unroll
        for (int nt = 0; nt < 8; nt++)
            #pragma unroll
            for (int r = 0; r < 4; r++) sacc[nt][r] = 0.f;

        #pragma unroll
        for (int ks = 0; ks < 4; ks++) {
            uint32_t kfh[8][2], kfl[8][2];
            #pragma unroll
            for (int p = 0; p < 4; p++) {
                uint32_t a = kA0 + (p * 16 * PADT_ + ks * 16) * 2;
                uint32_t al = kA0l + (p * 16 * PADT_ + ks * 16) * 2;
                LDSM4(kfh[2 * p][0], kfh[2 * p][1],
                      kfh[2 * p + 1][0], kfh[2 * p + 1][1], a);
                LDSM4(kfl[2 * p][0], kfl[2 * p][1],
                      kfl[2 * p + 1][0], kfl[2 * p + 1][1], al);
            }
            #pragma unroll
            for (int nt = 0; nt < 8; nt++) {
                MMA16816(sacc[nt], qfh[ks], kfh[nt]);
                MMA16816(sacc[nt], qfh[ks], kfl[nt]);
                MMA16816(sacc[nt], qfl[ks], kfh[nt]);
            }
        }

        // ---- scale + causal mask ----
        const float sc = 0.125f;
        if (k0 + 63 > row0) {
            #pragma unroll
            for (int nt = 0; nt < 8; nt++) {
                int c0 = k0 + nt * 8 + q2, c1 = c0 + 1;
                sacc[nt][0] = (c0 <= row0) ? sacc[nt][0] * sc : -1e30f;
                sacc[nt][1] = (c1 <= row0) ? sacc[nt][1] * sc : -1e30f;
                sacc[nt][2] = (c0 <= row1) ? sacc[nt][2] * sc : -1e30f;
                sacc[nt][3] = (c1 <= row1) ? sacc[nt][3] * sc : -1e30f;
            }
        } else {
            #pragma unroll
            for (int nt = 0; nt < 8; nt++)
                #pragma unroll
                for (int r = 0; r < 4; r++) sacc[nt][r] *= sc;
        }

        // ---- online softmax ----
        float rmax0 = -1e30f, rmax1 = -1e30f;
        #pragma unroll
        for (int nt = 0; nt < 8; nt++) {
            rmax0 = fmaxf(rmax0, fmaxf(sacc[nt][0], sacc[nt][1]));
            rmax1 = fmaxf(rmax1, fmaxf(sacc[nt][2], sacc[nt][3]));
        }
        rmax0 = fmaxf(rmax0, __shfl_xor_sync(0xffffffffu, rmax0, 1));
        rmax0 = fmaxf(rmax0, __shfl_xor_sync(0xffffffffu, rmax0, 2));
        rmax1 = fmaxf(rmax1, __shfl_xor_sync(0xffffffffu, rmax1, 1));
        rmax1 = fmaxf(rmax1, __shfl_xor_sync(0xffffffffu, rmax1, 2));
        float m0n = fmaxf(m0, rmax0), m1n = fmaxf(m1, rmax1);
        float corr0 = __expf(m0 - m0n), corr1 = __expf(m1 - m1n);
        float sum0 = 0.f, sum1 = 0.f;
        #pragma unroll
        for (int nt = 0; nt < 8; nt++) {
            sacc[nt][0] = __expf(sacc[nt][0] - m0n); sum0 += sacc[nt][0];
            sacc[nt][1] = __expf(sacc[nt][1] - m0n); sum0 += sacc[nt][1];
            sacc[nt][2] = __expf(sacc[nt][2] - m1n); sum1 += sacc[nt][2];
            sacc[nt][3] = __expf(sacc[nt][3] - m1n); sum1 += sacc[nt][3];
        }
        sum0 += __shfl_xor_sync(0xffffffffu, sum0, 1);
        sum0 += __shfl_xor_sync(0xffffffffu, sum0, 2);
        sum1 += __shfl_xor_sync(0xffffffffu, sum1, 1);
        sum1 += __shfl_xor_sync(0xffffffffu, sum1, 2);
        l0 = l0 * corr0 + sum0;  m0 = m0n;
        l1 = l1 * corr1 + sum1;  m1 = m1n;
        #pragma unroll
        for (int nt = 0; nt < 8; nt++) {
            oacc[nt][0] *= corr0; oacc[nt][1] *= corr0;
            oacc[nt][2] *= corr1; oacc[nt][3] *= corr1;
        }

        // ---- O += P V (P from registers; 3-term split) ----
        #pragma unroll
        for (int j = 0; j < 4; j++) {
            uint32_t ah[4], al[4];
            {
                float p0 = sacc[2 * j][0],     p1 = sacc[2 * j][1];
                float p2 = sacc[2 * j][2],     p3 = sacc[2 * j][3];
                float p4 = sacc[2 * j + 1][0], p5 = sacc[2 * j + 1][1];
                float p6 = sacc[2 * j + 1][2], p7 = sacc[2 * j + 1][3];
                ah[0] = pk2(p0, p1); ah[1] = pk2(p2, p3);
                ah[2] = pk2(p4, p5); ah[3] = pk2(p6, p7);
                al[0] = pk2(lo_of(p0), lo_of(p1)); al[1] = pk2(lo_of(p2), lo_of(p3));
                al[2] = pk2(lo_of(p4), lo_of(p5)); al[3] = pk2(lo_of(p6), lo_of(p7));
            }
            uint32_t vfh[8][2], vfl[8][2];
            #pragma unroll
            for (int p = 0; p < 4; p++) {
                uint32_t a = vA0 + (p * 16 * PADT_ + j * 16) * 2;
                uint32_t alo = vA0l + (p * 16 * PADT_ + j * 16) * 2;
                LDSM4(vfh[2 * p][0], vfh[2 * p][1],
                      vfh[2 * p + 1][0], vfh[2 * p + 1][1], a);
                LDSM4(vfl[2 * p][0], vfl[2 * p][1],
                      vfl[2 * p + 1][0], vfl[2 * p + 1][1], alo);
            }
            #pragma unroll
            for (int nt = 0; nt < 8; nt++) {
                MMA16816(oacc[nt], ah, vfh[nt]);
                MMA16816(oacc[nt], ah, vfl[nt]);
                MMA16816(oacc[nt], al, vfh[nt]);
            }
        }
        __syncthreads();   // all warps done with this stage before reuse
    }

    // ---- epilogue ----
    float inv0 = 1.0f / l0, inv1 = 1.0f / l1;
    size_t ob0 = ((size_t)(b * S_ + row0)) * D_ + h * DK_;
    size_t ob1 = ((size_t)(b * S_ + row1)) * D_ + h * DK_;
    #pragma unroll
    for (int nt = 0; nt < 8; nt++) {
        int col = nt * 8 + q2;
        float e0 = oacc[nt][0] * inv0, e1 = oacc[nt][1] * inv0;
        float e2 = oacc[nt][2] * inv1, e3 = oacc[nt][3] * inv1;
        *(uint32_t*)&g_ath[ob0 + col] = pk2(e0, e1);
        *(uint32_t*)&g_atl[ob0 + col] = pk2(lo_of(e0), lo_of(e1));
        *(uint32_t*)&g_ath[ob1 + col] = pk2(e2, e3);
        *(uint32_t*)&g_atl[ob1 + col] = pk2(lo_of(e2), lo_of(e3));
    }
}

// ---------------------------------------------------------------------------
extern "C" void kernel_launch(void* const* d_in, const int* in_sizes, int n_in,
                              void* d_out, int out_size) {
    const float* x    = (const float*)d_in[0];
    const float* Wqkv = (const float*)d_in[1];
    const float* Wo   = (const float*)d_in[2];
    float* out = (float*)d_out;

    float* qkv_p;
    cudaGetSymbolAddress((void**)&qkv_p, g_qkv);
    __nv_bfloat16 *xh, *xl, *wqh, *wql, *woh, *wol, *ath, *atl;
    cudaGetSymbolAddress((void**)&xh, g_xh);
    cudaGetSymbolAddress((void**)&xl, g_xl);
    cudaGetSymbolAddress((void**)&wqh, g_wqh);
    cudaGetSymbolAddress((void**)&wql, g_wql);
    cudaGetSymbolAddress((void**)&woh, g_woh);
    cudaGetSymbolAddress((void**)&wol, g_wol);
    cudaGetSymbolAddress((void**)&ath, g_ath);
    cudaGetSymbolAddress((void**)&atl, g_atl);

    cudaFuncSetAttribute(attn_mma, cudaFuncAttributeMaxDynamicSharedMemorySize,
                         ATT_SMEM_);
    cudaFuncSetAttribute(gemm_mma, cudaFuncAttributeMaxDynamicSharedMemorySize,
                         GEMM_SMEM_);

    // 1. RoPE tables
    rope_table_k<<<(S_ * QUARTER_ + 255) / 256, 256>>>();
    // 2. split inputs to bf16 hi/lo
    split_k<<<(MROWS_ * D_ / 4 + 255) / 256, 256>>>(x, xh, xl, MROWS_ * D_ / 4);
    split_k<<<(TD_ * D_ / 4 + 255) / 256, 256>>>(Wqkv, wqh, wql, TD_ * D_ / 4);
    split_k<<<(D_ * D_ / 4 + 255) / 256, 256>>>(Wo, woh, wol, D_ * D_ / 4);
    // 3. QKV projection: [4096,1024] x [3072,1024]^T -> fp32
    gemm_mma<<<dim3(TD_ / 128, MROWS_ / 128), 256, GEMM_SMEM_>>>(
        xh, xl, wqh, wql, qkv_p, TD_);
    // 4. RoPE + split + relayout q,k; V transpose+split
    prep_k<<<(B_ * H_ * S_ * 8 + 255) / 256, 256>>>();
    vtrans_k<<<dim3(S_ / 64, H_, B_), 256>>>();
    // 5. causal flash attention (tensor cores) -> split bf16 [bs][D]
    attn_mma<<<dim3(S_ / 128, H_, B_), 256, ATT_SMEM_>>>();
    // 6. output projection -> d_out
    gemm_mma<<<dim3(D_ / 128, MROWS_ / 128), 256, GEMM_SMEM_>>>(
        ath, atl, woh, wol, out, D_);
}

// round 16
// speedup vs baseline: 1.6075x; 1.6075x over previous
#include <cuda_runtime.h>
#include <cuda_bf16.h>
#include <math.h>
#include <stdint.h>

#define B_ 2
#define S_ 2048
#define D_ 1024
#define H_ 16
#define DK_ 64
#define TD_ 3072          // 3*D
#define MROWS_ 4096       // B*S
#define QUARTER_ 16
#define GK_ 1024          // K dim of both projections

// ---------------------------------------------------------------------------
// Scratch (device globals — no allocation allowed)
// ---------------------------------------------------------------------------
__device__ float g_qkv[B_ * S_ * TD_];   // [B,S,3D] fp32 (QKV GEMM output)
__device__ float g_cos[S_ * QUARTER_];
__device__ float g_sin[S_ * QUARTER_];
// bf16 split-precision operand buffers for projections
__device__ __nv_bfloat16 g_xh[MROWS_ * D_],  g_xl[MROWS_ * D_];
__device__ __nv_bfloat16 g_wqh[TD_ * D_],    g_wql[TD_ * D_];
__device__ __nv_bfloat16 g_woh[D_ * D_],     g_wol[D_ * D_];
__device__ __nv_bfloat16 g_ath[MROWS_ * D_], g_atl[MROWS_ * D_];
// attention operands, split hi/lo. q/k: [b,h,s,dk]. v: TRANSPOSED [b,h,dk,s].
#define QKVN_ (B_ * H_ * S_ * DK_)
__device__ __nv_bfloat16 g_qh[QKVN_], g_ql[QKVN_];
__device__ __nv_bfloat16 g_kh[QKVN_], g_kl[QKVN_];
__device__ __nv_bfloat16 g_vth[QKVN_], g_vtl[QKVN_];

// ---------------------------------------------------------------------------
// small helpers
// ---------------------------------------------------------------------------
__device__ __forceinline__ uint32_t pk2(float a, float b) {
    __nv_bfloat162 t = __floats2bfloat162_rn(a, b);
    return *reinterpret_cast<uint32_t*>(&t);
}
__device__ __forceinline__ float lo_of(float v) {
    return v - __bfloat162float(__float2bfloat16(v));
}
__device__ __forceinline__ uint32_t sm_u32(const void* p) {
    return (uint32_t)__cvta_generic_to_shared(p);
}

#define MMA16816(d, a, b) \
    asm volatile( \
        "mma.sync.aligned.m16n8k16.row.col.f32.bf16.bf16.f32 " \
        "{%0,%1,%2,%3}, {%4,%5,%6,%7}, {%8,%9}, {%0,%1,%2,%3};" \
        : "+f"((d)[0]), "+f"((d)[1]), "+f"((d)[2]), "+f"((d)[3]) \
        : "r"((a)[0]), "r"((a)[1]), "r"((a)[2]), "r"((a)[3]), \
          "r"((b)[0]), "r"((b)[1]))

#define LDSM4(r0, r1, r2, r3, addr) \
    asm volatile( \
        "ldmatrix.sync.aligned.m8n8.x4.shared.b16 {%0,%1,%2,%3}, [%4];" \
        : "=r"(r0), "=r"(r1), "=r"(r2), "=r"(r3) : "r"(addr))

// ---------------------------------------------------------------------------
// RoPE tables
// ---------------------------------------------------------------------------
__global__ void rope_table_k() {
    int i = blockIdx.x * blockDim.x + threadIdx.x;
    if (i >= S_ * QUARTER_) return;
    int s = i / QUARTER_;
    int j = i % QUARTER_;
    double ang = pow(1.0e-4, (double)j / (double)(QUARTER_ - 1));
    double th = (double)s * ang;
    g_cos[i] = (float)cos(th);
    g_sin[i] = (float)sin(th);
}

// ---------------------------------------------------------------------------
// fp32 -> (bf16 hi, bf16 lo) splitter
// ---------------------------------------------------------------------------
__global__ __launch_bounds__(256)
void split_k(const float* __restrict__ src, __nv_bfloat16* __restrict__ hi,
             __nv_bfloat16* __restrict__ lo, int n4) {
    int i = blockIdx.x * blockDim.x + threadIdx.x;
    if (i >= n4) return;
    float4 v = ((const float4*)src)[i];
    ((uint32_t*)hi)[2 * i + 0] = pk2(v.x, v.y);
    ((uint32_t*)hi)[2 * i + 1] = pk2(v.z, v.w);
    ((uint32_t*)lo)[2 * i + 0] = pk2(lo_of(v.x), lo_of(v.y));
    ((uint32_t*)lo)[2 * i + 1] = pk2(lo_of(v.z), lo_of(v.w));
}

// ---------------------------------------------------------------------------
// prep: RoPE + split q,k into [b,h,s,dk] (V handled by vtrans_k)
// ---------------------------------------------------------------------------
__device__ __forceinline__ void wr4(__nv_bfloat16* H, __nv_bfloat16* L,
                                    const float* v) {
    uint2 hh, ll;
    hh.x = pk2(v[0], v[1]); hh.y = pk2(v[2], v[3]);
    ll.x = pk2(lo_of(v[0]), lo_of(v[1]));
    ll.y = pk2(lo_of(v[2]), lo_of(v[3]));
    *(uint2*)H = hh;
    *(uint2*)L = ll;
}

__global__ __launch_bounds__(256)
void prep_k() {
    int idx = blockIdx.x * blockDim.x + threadIdx.x;
    if (idx >= B_ * H_ * S_ * 8) return;
    int t = idx & 7;
    int r = idx >> 3;
    int s = r & (S_ - 1); r >>= 11;
    int h = r & (H_ - 1);
    int b = r >> 4;
    int jj = (t < 4) ? (t << 2) : (16 + ((t - 4) << 2));
    size_t src = (size_t)(b * S_ + s) * TD_ + h * DK_;
    size_t dst = ((size_t)(b * H_ + h) * S_ + s) * DK_;

    float c[4], sn[4];
    bool dorope = jj < 16;
    if (dorope) {
        #pragma unroll
        for (int i = 0; i < 4; i++) {
            c[i]  = g_cos[s * QUARTER_ + jj + i];
            sn[i] = g_sin[s * QUARTER_ + jj + i];
        }
    }
    #pragma unroll
    for (int part = 0; part < 2; part++) {
        float4 x1 = *(const float4*)&g_qkv[src + part * D_ + jj];
        float4 x2 = *(const float4*)&g_qkv[src + part * D_ + jj + 32];
        float a[4] = {x1.x, x1.y, x1.z, x1.w};
        float bb[4] = {x2.x, x2.y, x2.z, x2.w};
        if (dorope) {
            #pragma unroll
            for (int i = 0; i < 4; i++) {
                float na = a[i] * c[i] - bb[i] * sn[i];
                float nb = a[i] * sn[i] + bb[i] * c[i];
                a[i] = na; bb[i] = nb;
            }
        }
        __nv_bfloat16* Hh = part ? g_kh : g_qh;
        __nv_bfloat16* Ll = part ? g_kl : g_ql;
        wr4(Hh + dst + jj, Ll + dst + jj, a);
        wr4(Hh + dst + jj + 32, Ll + dst + jj + 32, bb);
    }
}

// ---------------------------------------------------------------------------
// vtrans: V slice of g_qkv [b,s,2D+h*64+d] -> transposed split bf16 [b,h,d,s]
// One block per (64-s-tile, h, b); 64x64 tile through smem.
// ---------------------------------------------------------------------------
__global__ __launch_bounds__(256)
void vtrans_k() {
    __shared__ float tile[64 * 65];
    int b = blockIdx.z, h = blockIdx.y;
    int s0 = blockIdx.x << 6;
    int tid = threadIdx.x;
    int row = tid >> 2;          // 0..63
    int quar = tid & 3;          // 0..3

    {
        const float* src = g_qkv + (size_t)(b * S_ + s0 + row) * TD_ +
                           2 * D_ + h * DK_ + quar * 16;
        #pragma unroll
        for (int u = 0; u < 4; u++) {
            float4 v = *(const float4*)(src + u * 4);
            tile[(quar * 16 + u * 4 + 0) * 65 + row] = v.x;
            tile[(quar * 16 + u * 4 + 1) * 65 + row] = v.y;
            tile[(quar * 16 + u * 4 + 2) * 65 + row] = v.z;
            tile[(quar * 16 + u * 4 + 3) * 65 + row] = v.w;
        }
    }
    __syncthreads();
    {
        int d = row;
        size_t dst = ((size_t)(b * H_ + h) * DK_ + d) * S_ + s0 + quar * 16;
        #pragma unroll
        for (int u = 0; u < 4; u++) {
            float v0 = tile[d * 65 + quar * 16 + u * 4 + 0];
            float v1 = tile[d * 65 + quar * 16 + u * 4 + 1];
            float v2 = tile[d * 65 + quar * 16 + u * 4 + 2];
            float v3 = tile[d * 65 + quar * 16 + u * 4 + 3];
            uint2 hh, ll;
            hh.x = pk2(v0, v1); hh.y = pk2(v2, v3);
            ll.x = pk2(lo_of(v0), lo_of(v1)); ll.y = pk2(lo_of(v2), lo_of(v3));
            *(uint2*)&g_vth[dst + u * 4] = hh;
            *(uint2*)&g_vtl[dst + u * 4] = ll;
        }
    }
}

// ---------------------------------------------------------------------------
// mma.sync split-bf16 GEMM — round-14 register-staged pipeline (known good).
// ---------------------------------------------------------------------------
#define BK_ 32
#define ASTR_ 40
#define TILE_ELEMS_ (128 * ASTR_)
#define TILE_B_ (TILE_ELEMS_ * 2)

__device__ __forceinline__ void stage_load(
    uint4 st[8],
    const __nv_bfloat16* __restrict__ Ah, const __nv_bfloat16* __restrict__ Al,
    const __nv_bfloat16* __restrict__ Bh, const __nv_bfloat16* __restrict__ Bl,
    int bm, int bn, int kc, int tid) {
    #pragma unroll
    for (int u = 0; u < 8; u++) {
        int id = tid + (u << 8);
        int tile = id >> 9;
        int rem = id & 511;
        int row = rem >> 2;
        int seg = rem & 3;
        const __nv_bfloat16* src;
        if (tile == 0)      src = Ah + (size_t)(bm + row) * GK_;
        else if (tile == 1) src = Al + (size_t)(bm + row) * GK_;
        else if (tile == 2) src = Bh + (size_t)(bn + row) * GK_;
        else                src = Bl + (size_t)(bn + row) * GK_;
        st[u] = *(const uint4*)(src + kc + seg * 8);
    }
}

__global__ __launch_bounds__(256, 1)
void gemm_mma(const __nv_bfloat16* __restrict__ Ah, const __nv_bfloat16* __restrict__ Al,
              const __nv_bfloat16* __restrict__ Bh, const __nv_bfloat16* __restrict__ Bl,
              float* __restrict__ C, int N) {
    __shared__ __nv_bfloat16 smem[4 * TILE_ELEMS_];
    int tid = threadIdx.x;
    int lane = tid & 31, wid = tid >> 5;
    int warp_m = wid & 1;
    int warp_n = wid >> 1;
    int bm = blockIdx.y << 7, bn = blockIdx.x << 7;

    int g = lane >> 2;
    int tg2 = (lane & 3) << 1;

    uint32_t base_u = sm_u32(smem);
    int arow = ((lane >> 3) & 1) * 8 + (lane & 7);
    int acol = (lane >> 4) * 8;
    int brow = (lane >> 4) * 8 + (lane & 7);
    int bcol = ((lane >> 3) & 1) * 8;
    uint32_t aAddr0 = base_u + ((warp_m * 64 + arow) * ASTR_ + acol) * 2;
    uint32_t bAddr0 = base_u + 2 * TILE_B_ +
                      ((warp_n * 32 + brow) * ASTR_ + bcol) * 2;

    float acc[4][4][4];
    #pragma unroll
    for (int mt = 0; mt < 4; mt++)
        #pragma unroll
        for (int nt = 0; nt < 4; nt++)
            #pragma unroll
            for (int r = 0; r < 4; r++) acc[mt][nt][r] = 0.f;

    uint4 st[8];
    stage_load(st, Ah, Al, Bh, Bl, bm, bn, 0, tid);

    const int nchunks = GK_ / BK_;
    for (int c = 0; c < nchunks; c++) {
        __syncthreads();
        #pragma unroll
        for (int u = 0; u < 8; u++) {
            int id = tid + (u << 8);
            int tile = id >> 9;
            int rem = id & 511;
            int row = rem >> 2;
            int seg = rem & 3;
            *(uint4*)&smem[tile * TILE_ELEMS_ + row * ASTR_ + seg * 8] = st[u];
        }
        __syncthreads();
        if (c + 1 < nchunks)
            stage_load(st, Ah, Al, Bh, Bl, bm, bn, (c + 1) * BK_, tid);

        #pragma unroll
        for (int kk = 0; kk < 2; kk++) {
            uint32_t koff = kk * 16 * 2;
            uint32_t ahf[4][4], alf[4][4], bhf[4][2], blf[4][2];
            #pragma unroll
            for (int mt = 0; mt < 4; mt++) {
                uint32_t a = aAddr0 + mt * (16 * ASTR_ * 2) + koff;
                LDSM4(ahf[mt][0], ahf[mt][1], ahf[mt][2], ahf[mt][3], a);
                LDSM4(alf[mt][0], alf[mt][1], alf[mt][2], alf[mt][3],
                      a + TILE_B_);
            }
            #pragma unroll
            for (int p = 0; p < 2; p++) {
                uint32_t bA = bAddr0 + p * (16 * ASTR_ * 2) + koff;
                LDSM4(bhf[2 * p][0], bhf[2 * p][1],
                      bhf[2 * p + 1][0], bhf[2 * p + 1][1], bA);
                LDSM4(blf[2 * p][0], blf[2 * p][1],
                      blf[2 * p + 1][0], blf[2 * p + 1][1], bA + TILE_B_);
            }
            #pragma unroll
            for (int mt = 0; mt < 4; mt++)
                #pragma unroll
                for (int nt = 0; nt < 4; nt++) {
                    MMA16816(acc[mt][nt], ahf[mt], bhf[nt]);
                    MMA16816(acc[mt][nt], ahf[mt], blf[nt]);
                    MMA16816(acc[mt][nt], alf[mt], bhf[nt]);
                }
        }
    }

    #pragma unroll
    for (int mt = 0; mt < 4; mt++) {
        int m = bm + warp_m * 64 + mt * 16 + g;
        #pragma unroll
        for (int nt = 0; nt < 4; nt++) {
            int n = bn + warp_n * 32 + nt * 8 + tg2;
            *(float2*)&C[(size_t)m * N + n] =
                make_float2(acc[mt][nt][0], acc[mt][nt][1]);
            *(float2*)&C[(size_t)(m + 8) * N + n] =
                make_float2(acc[mt][nt][2], acc[mt][nt][3]);
        }
    }
}

// ---------------------------------------------------------------------------
// Flash attention: mma.sync split-bf16 + ldmatrix.
// Register-staged KV prefetch (GEMM round-14 pattern): LDGs for tile kt+1 fly
// during tile kt's compute. V pre-transposed in gmem -> straight uint4 loads.
// CTA: 128 q-rows for one (b,h). 8 warps, single KV smem buffer.
// ---------------------------------------------------------------------------
#define PADT_ 72
#define ATT_SMEM_ ((2 * 128 + 4 * 64) * PADT_ * 2)   // 73728 bytes

__device__ __forceinline__ void kv_load(uint4 st[8], size_t base, size_t baseT,
                                        int k0, int tid) {
    #pragma unroll
    for (int u = 0; u < 8; u++) {
        int id = tid + (u << 8);
        int tile = id >> 9;      // 0:Kh 1:Kl 2:Vh 3:Vl
        int rem = id & 511;
        int row = rem >> 3;      // key row (K) / d row (V)
        int seg = rem & 7;
        const __nv_bfloat16* src;
        if (tile == 0)      src = g_kh + base + (size_t)(k0 + row) * DK_ + seg * 8;
        else if (tile == 1) src = g_kl + base + (size_t)(k0 + row) * DK_ + seg * 8;
        else if (tile == 2) src = g_vth + baseT + (size_t)row * S_ + k0 + seg * 8;
        else                src = g_vtl + baseT + (size_t)row * S_ + k0 + seg * 8;
        st[u] = *(const uint4*)src;
    }
}

__global__ __launch_bounds__(256, 1)
void attn_mma() {
    extern __shared__ __nv_bfloat16 smb[];
    __nv_bfloat16* sQh = smb;
    __nv_bfloat16* sQl = sQh + 128 * PADT_;
    __nv_bfloat16* sKV = sQl + 128 * PADT_;   // Kh,Kl,Vh,Vl each 64*PADT_

    int tid = threadIdx.x;
    int lane = tid & 31, w = tid >> 5;
    int g = lane >> 2;
    int q2 = (lane & 3) << 1;
    int b = blockIdx.z, h = blockIdx.y;
    int qt = (int)gridDim.x - 1 - (int)blockIdx.x;   // heavy tiles first
    int q0 = qt << 7;
    size_t base = ((size_t)(b * H_ + h)) * S_ * DK_;
    size_t baseT = ((size_t)(b * H_ + h)) * DK_ * S_;

    int brow = (lane >> 4) * 8 + (lane & 7);
    int bcol = ((lane >> 3) & 1) * 8;
    uint32_t sKV_u = sm_u32(sKV);
    uint32_t kA0  = sKV_u + (brow * PADT_ + bcol) * 2;
    uint32_t kA0l = kA0 + 64 * PADT_ * 2;
    uint32_t vA0  = kA0 + 2 * 64 * PADT_ * 2;
    uint32_t vA0l = kA0 + 3 * 64 * PADT_ * 2;

    // ---- load Q tile (128 x 64) hi/lo into smem ----
    {
        int row = tid >> 1;
        int half = (tid & 1) << 2;
        const uint4* gh = (const uint4*)(g_qh + base + (size_t)(q0 + row) * DK_);
        const uint4* gl = (const uint4*)(g_ql + base + (size_t)(q0 + row) * DK_);
        uint4* dh = (uint4*)(sQh + row * PADT_);
        uint4* dl = (uint4*)(sQl + row * PADT_);
        #pragma unroll
        for (int u = 0; u < 4; u++) {
            dh[half + u] = gh[half + u];
            dl[half + u] = gl[half + u];
        }
    }

    // prefetch KV tile 0 into registers while Q smem settles
    uint4 st[8];
    kv_load(st, base, baseT, 0, tid);
    __syncthreads();

    // ---- hoist Q fragments ----
    uint32_t qfh[4][4], qfl[4][4];
    {
        int arow = ((lane >> 3) & 1) * 8 + (lane & 7);
        int acol = (lane >> 4) * 8;
        uint32_t qh_u = sm_u32(sQh) + ((w * 16 + arow) * PADT_ + acol) * 2;
        uint32_t ql_u = sm_u32(sQl) + ((w * 16 + arow) * PADT_ + acol) * 2;
        #pragma unroll
        for (int ks = 0; ks < 4; ks++) {
            LDSM4(qfh[ks][0], qfh[ks][1], qfh[ks][2], qfh[ks][3],
                  qh_u + ks * 32);
            LDSM4(qfl[ks][0], qfl[ks][1], qfl[ks][2], qfl[ks][3],
                  ql_u + ks * 32);
        }
    }

    float oacc[8][4];
    #pragma unroll
    for (int nt = 0; nt < 8; nt++)
        #pragma unroll
        for (int r = 0; r < 4; r++) oacc[nt][r] = 0.f;
    float m0 = -1e30f, m1 = -1e30f, l0 = 0.f, l1 = 0.f;
    int row0 = q0 + w * 16 + g, row1 = row0 + 8;

    int nkt = 2 * (qt + 1);
    for (int kt = 0; kt < nkt; kt++) {
        int k0 = kt << 6;
        __syncthreads();   // prior tile's compute done reading sKV
        // store staged KV regs -> smem
        #pragma unroll
        for (int u = 0; u < 8; u++) {
            int id = tid + (u << 8);
            int tile = id >> 9;
            int rem = id & 511;
            int row = rem >> 3;
            int seg = rem & 7;
            *(uint4*)&sKV[tile * 64 * PADT_ + row * PADT_ + seg * 8] = st[u];
        }
        __syncthreads();
        // prefetch next tile (LDGs overlap this tile's compute)
        if (kt + 1 < nkt)
            kv_load(st, base, baseT, (kt + 1) << 6, tid);

        // ---- S = Q K^T (3-term split) ----
        float sacc[8][4];
        #pragma unroll
        for (int nt = 0; nt < 8; nt++)
            #pragma unroll
            for (int r = 0; r < 4; r++) sacc[nt][r] = 0.f;

        #pragma unroll
        for (int ks = 0; ks < 4; ks++) {
            uint32_t kfh[8][2], kfl[8][2];
            #pragma unroll
            for (int p = 0; p < 4; p++) {
                uint32_t a = kA0 + (p * 16 * PADT_ + ks * 16) * 2;
                uint32_t al = kA0l + (p * 16 * PADT_ + ks * 16) * 2;
                LDSM4(kfh[2 * p][0], kfh[2 * p][1],
                      kfh[2 * p + 1][0], kfh[2 * p + 1][1], a);
                LDSM4(kfl[2 * p][0], kfl[2 * p][1],
                      kfl[2 * p + 1][0], kfl[2 * p + 1][1], al);
            }
            #pragma unroll
            for (int nt = 0; nt < 8; nt++) {
                MMA16816(sacc[nt], qfh[ks], kfh[nt]);
                MMA16816(sacc[nt], qfh[ks], kfl[nt]);
                MMA16816(sacc[nt], qfl[ks], kfh[nt]);
            }
        }

        // ---- scale + causal mask ----
        const float sc = 0.125f;
        if (k0 + 63 > row0) {
            #pragma unroll
            for (int nt = 0; nt < 8; nt++) {
                int c0 = k0 + nt * 8 + q2, c1 = c0 + 1;
                sacc[nt][0] = (c0 <= row0) ? sacc[nt][0] * sc : -1e30f;
                sacc[nt][1] = (c1 <= row0) ? sacc[nt][1] * sc : -1e30f;
                sacc[nt][2] = (c0 <= row1) ? sacc[nt][2] * sc : -1e30f;
                sacc[nt][3] = (c1 <= row1) ? sacc[nt][3] * sc : -1e30f;
            }
        } else {
            #pragma unroll
            for (int nt = 0; nt < 8; nt++)
                #pragma unroll
                for (int r = 0; r < 4; r++) sacc[nt][r] *= sc;
        }

        // ---- online softmax ----
        float rmax0 = -1e30f, rmax1 = -1e30f;
        #pragma unroll
        for (int nt = 0; nt < 8; nt++) {
            rmax0 = fmaxf(rmax0, fmaxf(sacc[nt][0], sacc[nt][1]));
            rmax1 = fmaxf(rmax1, fmaxf(sacc[nt][2], sacc[nt][3]));
        }
        rmax0 = fmaxf(rmax0, __shfl_xor_sync(0xffffffffu, rmax0, 1));
        rmax0 = fmaxf(rmax0, __shfl_xor_sync(0xffffffffu, rmax0, 2));
        rmax1 = fmaxf(rmax1, __shfl_xor_sync(0xffffffffu, rmax1, 1));
        rmax1 = fmaxf(rmax1, __shfl_xor_sync(0xffffffffu, rmax1, 2));
        float m0n = fmaxf(m0, rmax0), m1n = fmaxf(m1, rmax1);
        float corr0 = __expf(m0 - m0n), corr1 = __expf(m1 - m1n);
        float sum0 = 0.f, sum1 = 0.f;
        #pragma unroll
        for (int nt = 0; nt < 8; nt++) {
            sacc[nt][0] = __expf(sacc[nt][0] - m0n); sum0 += sacc[nt][0];
            sacc[nt][1] = __expf(sacc[nt][1] - m0n); sum0 += sacc[nt][1];
            sacc[nt][2] = __expf(sacc[nt][2] - m1n); sum1 += sacc[nt][2];
            sacc[nt][3] = __expf(sacc[nt][3] - m1n); sum1 += sacc[nt][3];
        }
        sum0 += __shfl_xor_sync(0xffffffffu, sum0, 1);
        sum0 += __shfl_xor_sync(0xffffffffu, sum0, 2);
        sum1 += __shfl_xor_sync(0xffffffffu, sum1, 1);
        sum1 += __shfl_xor_sync(0xffffffffu, sum1, 2);
        l0 = l0 * corr0 + sum0;  m0 = m0n;
        l1 = l1 * corr1 + sum1;  m1 = m1n;
        #pragma unroll
        for (int nt = 0; nt < 8; nt++) {
            oacc[nt][0] *= corr0; oacc[nt][1] *= corr0;
            oacc[nt][2] *= corr1; oacc[nt][3] *= corr1;
        }

        // ---- O += P V (P from registers; 3-term split) ----
        #pragma unroll
        for (int j = 0; j < 4; j++) {
            uint32_t ah[4], al[4];
            {
                float p0 = sacc[2 * j][0],     p1 = sacc[2 * j][1];
                float p2 = sacc[2 * j][2],     p3 = sacc[2 * j][3];
                float p4 = sacc[2 * j + 1][0], p5 = sacc[2 * j + 1][1];
                float p6 = sacc[2 * j + 1][2], p7 = sacc[2 * j + 1][3];
                ah[0] = pk2(p0, p1); ah[1] = pk2(p2, p3);
                ah[2] = pk2(p4, p5); ah[3] = pk2(p6, p7);
                al[0] = pk2(lo_of(p0), lo_of(p1)); al[1] = pk2(lo_of(p2), lo_of(p3));
                al[2] = pk2(lo_of(p4), lo_of(p5)); al[3] = pk2(lo_of(p6), lo_of(p7));
            }
            uint32_t vfh[8][2], vfl[8][2];
            #pragma unroll
            for (int p = 0; p < 4; p++) {
                uint32_t a = vA0 + (p * 16 * PADT_ + j * 16) * 2;
                uint32_t alo = vA0l + (p * 16 * PADT_ + j * 16) * 2;
                LDSM4(vfh[2 * p][0], vfh[2 * p][1],
                      vfh[2 * p + 1][0], vfh[2 * p + 1][1], a);
                LDSM4(vfl[2 * p][0], vfl[2 * p][1],
                      vfl[2 * p + 1][0], vfl[2 * p + 1][1], alo);
            }
            #pragma unroll
            for (int nt = 0; nt < 8; nt++) {
                MMA16816(oacc[nt], ah, vfh[nt]);
                MMA16816(oacc[nt], ah, vfl[nt]);
                MMA16816(oacc[nt], al, vfh[nt]);
            }
        }
    }

    // ---- epilogue ----
    float inv0 = 1.0f / l0, inv1 = 1.0f / l1;
    size_t ob0 = ((size_t)(b * S_ + row0)) * D_ + h * DK_;
    size_t ob1 = ((size_t)(b * S_ + row1)) * D_ + h * DK_;
    #pragma unroll
    for (int nt = 0; nt < 8; nt++) {
        int col = nt * 8 + q2;
        float e0 = oacc[nt][0] * inv0, e1 = oacc[nt][1] * inv0;
        float e2 = oacc[nt][2] * inv1, e3 = oacc[nt][3] * inv1;
        *(uint32_t*)&g_ath[ob0 + col] = pk2(e0, e1);
        *(uint32_t*)&g_atl[ob0 + col] = pk2(lo_of(e0), lo_of(e1));
        *(uint32_t*)&g_ath[ob1 + col] = pk2(e2, e3);
        *(uint32_t*)&g_atl[ob1 + col] = pk2(lo_of(e2), lo_of(e3));
    }
}

// ---------------------------------------------------------------------------
extern "C" void kernel_launch(void* const* d_in, const int* in_sizes, int n_in,
                              void* d_out, int out_size) {
    const float* x    = (const float*)d_in[0];
    const float* Wqkv = (const float*)d_in[1];
    const float* Wo   = (const float*)d_in[2];
    float* out = (float*)d_out;

    float* qkv_p;
    cudaGetSymbolAddress((void**)&qkv_p, g_qkv);
    __nv_bfloat16 *xh, *xl, *wqh, *wql, *woh, *wol, *ath, *atl;
    cudaGetSymbolAddress((void**)&xh, g_xh);
    cudaGetSymbolAddress((void**)&xl, g_xl);
    cudaGetSymbolAddress((void**)&wqh, g_wqh);
    cudaGetSymbolAddress((void**)&wql, g_wql);
    cudaGetSymbolAddress((void**)&woh, g_woh);
    cudaGetSymbolAddress((void**)&wol, g_wol);
    cudaGetSymbolAddress((void**)&ath, g_ath);
    cudaGetSymbolAddress((void**)&atl, g_atl);

    cudaFuncSetAttribute(attn_mma, cudaFuncAttributeMaxDynamicSharedMemorySize,
                         ATT_SMEM_);

    // 1. RoPE tables
    rope_table_k<<<(S_ * QUARTER_ + 255) / 256, 256>>>();
    // 2. split inputs to bf16 hi/lo
    split_k<<<(MROWS_ * D_ / 4 + 255) / 256, 256>>>(x, xh, xl, MROWS_ * D_ / 4);
    split_k<<<(TD_ * D_ / 4 + 255) / 256, 256>>>(Wqkv, wqh, wql, TD_ * D_ / 4);
    split_k<<<(D_ * D_ / 4 + 255) / 256, 256>>>(Wo, woh, wol, D_ * D_ / 4);
    // 3. QKV projection: [4096,1024] x [3072,1024]^T -> fp32
    gemm_mma<<<dim3(TD_ / 128, MROWS_ / 128), 256>>>(xh, xl, wqh, wql,
                                                     qkv_p, TD_);
    // 4. RoPE + split + relayout q,k; V transpose+split
    prep_k<<<(B_ * H_ * S_ * 8 + 255) / 256, 256>>>();
    vtrans_k<<<dim3(S_ / 64, H_, B_), 256>>>();
    // 5. causal flash attention (tensor cores) -> split bf16 [bs][D]
    attn_mma<<<dim3(S_ / 128, H_, B_), 256, ATT_SMEM_>>>();
    // 6. output projection -> d_out
    gemm_mma<<<dim3(D_ / 128, MROWS_ / 128), 256>>>(ath, atl, woh, wol,
                                                    out, D_);
}

// round 17
// speedup vs baseline: 1.6727x; 1.0405x over previous
#include <cuda_runtime.h>
#include <cuda_bf16.h>
#include <math.h>
#include <stdint.h>

#define B_ 2
#define S_ 2048
#define D_ 1024
#define H_ 16
#define DK_ 64
#define TD_ 3072          // 3*D
#define MROWS_ 4096       // B*S
#define QUARTER_ 16
#define GK_ 1024          // K dim of both projections

// ---------------------------------------------------------------------------
// Scratch (device globals — no allocation allowed)
// ---------------------------------------------------------------------------
__device__ float g_qkv[B_ * S_ * TD_];   // [B,S,3D] fp32 (QKV GEMM output)
__device__ float g_cos[S_ * QUARTER_];
__device__ float g_sin[S_ * QUARTER_];
// bf16 split-precision operand buffers for projections
__device__ __nv_bfloat16 g_xh[MROWS_ * D_],  g_xl[MROWS_ * D_];
__device__ __nv_bfloat16 g_wqh[TD_ * D_],    g_wql[TD_ * D_];
__device__ __nv_bfloat16 g_woh[D_ * D_],     g_wol[D_ * D_];
__device__ __nv_bfloat16 g_ath[MROWS_ * D_], g_atl[MROWS_ * D_];
// attention operands, split hi/lo. q/k: [b,h,s,dk]. v: TRANSPOSED [b,h,dk,s].
#define QKVN_ (B_ * H_ * S_ * DK_)
__device__ __nv_bfloat16 g_qh[QKVN_], g_ql[QKVN_];
__device__ __nv_bfloat16 g_kh[QKVN_], g_kl[QKVN_];
__device__ __nv_bfloat16 g_vth[QKVN_], g_vtl[QKVN_];

// ---------------------------------------------------------------------------
// small helpers
// ---------------------------------------------------------------------------
__device__ __forceinline__ uint32_t pk2(float a, float b) {
    __nv_bfloat162 t = __floats2bfloat162_rn(a, b);
    return *reinterpret_cast<uint32_t*>(&t);
}
__device__ __forceinline__ float lo_of(float v) {
    return v - __bfloat162float(__float2bfloat16(v));
}
__device__ __forceinline__ uint32_t sm_u32(const void* p) {
    return (uint32_t)__cvta_generic_to_shared(p);
}

#define MMA16816(d, a, b) \
    asm volatile( \
        "mma.sync.aligned.m16n8k16.row.col.f32.bf16.bf16.f32 " \
        "{%0,%1,%2,%3}, {%4,%5,%6,%7}, {%8,%9}, {%0,%1,%2,%3};" \
        : "+f"((d)[0]), "+f"((d)[1]), "+f"((d)[2]), "+f"((d)[3]) \
        : "r"((a)[0]), "r"((a)[1]), "r"((a)[2]), "r"((a)[3]), \
          "r"((b)[0]), "r"((b)[1]))

#define LDSM4(r0, r1, r2, r3, addr) \
    asm volatile( \
        "ldmatrix.sync.aligned.m8n8.x4.shared.b16 {%0,%1,%2,%3}, [%4];" \
        : "=r"(r0), "=r"(r1), "=r"(r2), "=r"(r3) : "r"(addr))

// ---------------------------------------------------------------------------
// RoPE tables
// ---------------------------------------------------------------------------
__global__ void rope_table_k() {
    int i = blockIdx.x * blockDim.x + threadIdx.x;
    if (i >= S_ * QUARTER_) return;
    int s = i / QUARTER_;
    int j = i % QUARTER_;
    double ang = pow(1.0e-4, (double)j / (double)(QUARTER_ - 1));
    double th = (double)s * ang;
    g_cos[i] = (float)cos(th);
    g_sin[i] = (float)sin(th);
}

// ---------------------------------------------------------------------------
// fused fp32 -> (bf16 hi, lo) splitter for x, Wqkv, Wo in one launch
// ---------------------------------------------------------------------------
#define N4_X_  (MROWS_ * D_ / 4)          // 1048576
#define N4_WQ_ (TD_ * D_ / 4)             // 786432
#define N4_WO_ (D_ * D_ / 4)              // 262144
#define N4_TOT_ (N4_X_ + N4_WQ_ + N4_WO_)

__global__ __launch_bounds__(256)
void split3_k(const float* __restrict__ x,
              const float* __restrict__ wq,
              const float* __restrict__ wo) {
    int i = blockIdx.x * blockDim.x + threadIdx.x;
    if (i >= N4_TOT_) return;
    const float* src;
    __nv_bfloat16 *hi, *lo;
    int j;
    if (i < N4_X_) {
        src = x; hi = g_xh; lo = g_xl; j = i;
    } else if (i < N4_X_ + N4_WQ_) {
        src = wq; hi = g_wqh; lo = g_wql; j = i - N4_X_;
    } else {
        src = wo; hi = g_woh; lo = g_wol; j = i - N4_X_ - N4_WQ_;
    }
    float4 v = ((const float4*)src)[j];
    ((uint32_t*)hi)[2 * j + 0] = pk2(v.x, v.y);
    ((uint32_t*)hi)[2 * j + 1] = pk2(v.z, v.w);
    ((uint32_t*)lo)[2 * j + 0] = pk2(lo_of(v.x), lo_of(v.y));
    ((uint32_t*)lo)[2 * j + 1] = pk2(lo_of(v.z), lo_of(v.w));
}

// fp32 -> split for attention output (unchanged single-array form)
__global__ __launch_bounds__(256)
void split_k(const float* __restrict__ src, __nv_bfloat16* __restrict__ hi,
             __nv_bfloat16* __restrict__ lo, int n4) {
    int i = blockIdx.x * blockDim.x + threadIdx.x;
    if (i >= n4) return;
    float4 v = ((const float4*)src)[i];
    ((uint32_t*)hi)[2 * i + 0] = pk2(v.x, v.y);
    ((uint32_t*)hi)[2 * i + 1] = pk2(v.z, v.w);
    ((uint32_t*)lo)[2 * i + 0] = pk2(lo_of(v.x), lo_of(v.y));
    ((uint32_t*)lo)[2 * i + 1] = pk2(lo_of(v.z), lo_of(v.w));
}

// ---------------------------------------------------------------------------
// prep: RoPE + split q,k into [b,h,s,dk] (V handled by vtrans_k)
// ---------------------------------------------------------------------------
__device__ __forceinline__ void wr4(__nv_bfloat16* H, __nv_bfloat16* L,
                                    const float* v) {
    uint2 hh, ll;
    hh.x = pk2(v[0], v[1]); hh.y = pk2(v[2], v[3]);
    ll.x = pk2(lo_of(v[0]), lo_of(v[1]));
    ll.y = pk2(lo_of(v[2]), lo_of(v[3]));
    *(uint2*)H = hh;
    *(uint2*)L = ll;
}

__global__ __launch_bounds__(256)
void prep_k() {
    int idx = blockIdx.x * blockDim.x + threadIdx.x;
    if (idx >= B_ * H_ * S_ * 8) return;
    int t = idx & 7;
    int r = idx >> 3;
    int s = r & (S_ - 1); r >>= 11;
    int h = r & (H_ - 1);
    int b = r >> 4;
    int jj = (t < 4) ? (t << 2) : (16 + ((t - 4) << 2));
    size_t src = (size_t)(b * S_ + s) * TD_ + h * DK_;
    size_t dst = ((size_t)(b * H_ + h) * S_ + s) * DK_;

    float c[4], sn[4];
    bool dorope = jj < 16;
    if (dorope) {
        #pragma unroll
        for (int i = 0; i < 4; i++) {
            c[i]  = g_cos[s * QUARTER_ + jj + i];
            sn[i] = g_sin[s * QUARTER_ + jj + i];
        }
    }
    #pragma unroll
    for (int part = 0; part < 2; part++) {
        float4 x1 = *(const float4*)&g_qkv[src + part * D_ + jj];
        float4 x2 = *(const float4*)&g_qkv[src + part * D_ + jj + 32];
        float a[4] = {x1.x, x1.y, x1.z, x1.w};
        float bb[4] = {x2.x, x2.y, x2.z, x2.w};
        if (dorope) {
            #pragma unroll
            for (int i = 0; i < 4; i++) {
                float na = a[i] * c[i] - bb[i] * sn[i];
                float nb = a[i] * sn[i] + bb[i] * c[i];
                a[i] = na; bb[i] = nb;
            }
        }
        __nv_bfloat16* Hh = part ? g_kh : g_qh;
        __nv_bfloat16* Ll = part ? g_kl : g_ql;
        wr4(Hh + dst + jj, Ll + dst + jj, a);
        wr4(Hh + dst + jj + 32, Ll + dst + jj + 32, bb);
    }
}

// ---------------------------------------------------------------------------
// vtrans: V slice of g_qkv -> transposed split bf16 [b,h,d,s]
// ---------------------------------------------------------------------------
__global__ __launch_bounds__(256)
void vtrans_k() {
    __shared__ float tile[64 * 65];
    int b = blockIdx.z, h = blockIdx.y;
    int s0 = blockIdx.x << 6;
    int tid = threadIdx.x;
    int row = tid >> 2;
    int quar = tid & 3;

    {
        const float* src = g_qkv + (size_t)(b * S_ + s0 + row) * TD_ +
                           2 * D_ + h * DK_ + quar * 16;
        #pragma unroll
        for (int u = 0; u < 4; u++) {
            float4 v = *(const float4*)(src + u * 4);
            tile[(quar * 16 + u * 4 + 0) * 65 + row] = v.x;
            tile[(quar * 16 + u * 4 + 1) * 65 + row] = v.y;
            tile[(quar * 16 + u * 4 + 2) * 65 + row] = v.z;
            tile[(quar * 16 + u * 4 + 3) * 65 + row] = v.w;
        }
    }
    __syncthreads();
    {
        int d = row;
        size_t dst = ((size_t)(b * H_ + h) * DK_ + d) * S_ + s0 + quar * 16;
        #pragma unroll
        for (int u = 0; u < 4; u++) {
            float v0 = tile[d * 65 + quar * 16 + u * 4 + 0];
            float v1 = tile[d * 65 + quar * 16 + u * 4 + 1];
            float v2 = tile[d * 65 + quar * 16 + u * 4 + 2];
            float v3 = tile[d * 65 + quar * 16 + u * 4 + 3];
            uint2 hh, ll;
            hh.x = pk2(v0, v1); hh.y = pk2(v2, v3);
            ll.x = pk2(lo_of(v0), lo_of(v1)); ll.y = pk2(lo_of(v2), lo_of(v3));
            *(uint2*)&g_vth[dst + u * 4] = hh;
            *(uint2*)&g_vtl[dst + u * 4] = ll;
        }
    }
}

// ---------------------------------------------------------------------------
// mma.sync split-bf16 GEMM — register-staged LDG prefetch + double-buffered
// smem, ONE barrier per chunk. CTA 128x128, BK=32, 8 warps.
// ---------------------------------------------------------------------------
#define BK_ 32
#define ASTR_ 40
#define TILE_ELEMS_ (128 * ASTR_)
#define TILE_B_ (TILE_ELEMS_ * 2)
#define GSTG_E_ (4 * TILE_ELEMS_)          // elems per stage
#define GSTG_B_ (GSTG_E_ * 2)              // 40960 bytes
#define GEMM_SMEM_ (2 * GSTG_B_)           // 81920

__device__ __forceinline__ void stage_load(
    uint4 st[8],
    const __nv_bfloat16* __restrict__ Ah, const __nv_bfloat16* __restrict__ Al,
    const __nv_bfloat16* __restrict__ Bh, const __nv_bfloat16* __restrict__ Bl,
    int bm, int bn, int kc, int tid) {
    #pragma unroll
    for (int u = 0; u < 8; u++) {
        int id = tid + (u << 8);
        int tile = id >> 9;
        int rem = id & 511;
        int row = rem >> 2;
        int seg = rem & 3;
        const __nv_bfloat16* src;
        if (tile == 0)      src = Ah + (size_t)(bm + row) * GK_;
        else if (tile == 1) src = Al + (size_t)(bm + row) * GK_;
        else if (tile == 2) src = Bh + (size_t)(bn + row) * GK_;
        else                src = Bl + (size_t)(bn + row) * GK_;
        st[u] = *(const uint4*)(src + kc + seg * 8);
    }
}

__device__ __forceinline__ void stage_sts(__nv_bfloat16* smg, const uint4 st[8],
                                          int stage, int tid) {
    __nv_bfloat16* dst = smg + stage * GSTG_E_;
    #pragma unroll
    for (int u = 0; u < 8; u++) {
        int id = tid + (u << 8);
        int tile = id >> 9;
        int rem = id & 511;
        int row = rem >> 2;
        int seg = rem & 3;
        *(uint4*)&dst[tile * TILE_ELEMS_ + row * ASTR_ + seg * 8] = st[u];
    }
}

__global__ __launch_bounds__(256, 1)
void gemm_mma(const __nv_bfloat16* __restrict__ Ah, const __nv_bfloat16* __restrict__ Al,
              const __nv_bfloat16* __restrict__ Bh, const __nv_bfloat16* __restrict__ Bl,
              float* __restrict__ C, int N) {
    extern __shared__ __nv_bfloat16 smg[];
    int tid = threadIdx.x;
    int lane = tid & 31, wid = tid >> 5;
    int warp_m = wid & 1;
    int warp_n = wid >> 1;
    int bm = blockIdx.y << 7, bn = blockIdx.x << 7;

    int g = lane >> 2;
    int tg2 = (lane & 3) << 1;

    uint32_t base_u = sm_u32(smg);
    int arow = ((lane >> 3) & 1) * 8 + (lane & 7);
    int acol = (lane >> 4) * 8;
    int brow = (lane >> 4) * 8 + (lane & 7);
    int bcol = ((lane >> 3) & 1) * 8;
    uint32_t aAddr0 = base_u + ((warp_m * 64 + arow) * ASTR_ + acol) * 2;
    uint32_t bAddr0 = base_u + 2 * TILE_B_ +
                      ((warp_n * 32 + brow) * ASTR_ + bcol) * 2;

    float acc[4][4][4];
    #pragma unroll
    for (int mt = 0; mt < 4; mt++)
        #pragma unroll
        for (int nt = 0; nt < 4; nt++)
            #pragma unroll
            for (int r = 0; r < 4; r++) acc[mt][nt][r] = 0.f;

    uint4 st[8];
    stage_load(st, Ah, Al, Bh, Bl, bm, bn, 0, tid);
    stage_sts(smg, st, 0, tid);
    __syncthreads();

    const int nchunks = GK_ / BK_;
    for (int c = 0; c < nchunks; c++) {
        if (c + 1 < nchunks)
            stage_load(st, Ah, Al, Bh, Bl, bm, bn, (c + 1) * BK_, tid);

        uint32_t soff = (c & 1) * GSTG_B_;
        #pragma unroll
        for (int kk = 0; kk < 2; kk++) {
            uint32_t koff = soff + kk * 16 * 2;
            uint32_t ahf[4][4], alf[4][4], bhf[4][2], blf[4][2];
            #pragma unroll
            for (int mt = 0; mt < 4; mt++) {
                uint32_t a = aAddr0 + mt * (16 * ASTR_ * 2) + koff;
                LDSM4(ahf[mt][0], ahf[mt][1], ahf[mt][2], ahf[mt][3], a);
                LDSM4(alf[mt][0], alf[mt][1], alf[mt][2], alf[mt][3],
                      a + TILE_B_);
            }
            #pragma unroll
            for (int p = 0; p < 2; p++) {
                uint32_t bA = bAddr0 + p * (16 * ASTR_ * 2) + koff;
                LDSM4(bhf[2 * p][0], bhf[2 * p][1],
                      bhf[2 * p + 1][0], bhf[2 * p + 1][1], bA);
                LDSM4(blf[2 * p][0], blf[2 * p][1],
                      blf[2 * p + 1][0], blf[2 * p + 1][1], bA + TILE_B_);
            }
            #pragma unroll
            for (int mt = 0; mt < 4; mt++)
                #pragma unroll
                for (int nt = 0; nt < 4; nt++) {
                    MMA16816(acc[mt][nt], ahf[mt], bhf[nt]);
                    MMA16816(acc[mt][nt], ahf[mt], blf[nt]);
                    MMA16816(acc[mt][nt], alf[mt], bhf[nt]);
                }
        }
        if (c + 1 < nchunks)
            stage_sts(smg, st, (c + 1) & 1, tid);
        __syncthreads();
    }

    #pragma unroll
    for (int mt = 0; mt < 4; mt++) {
        int m = bm + warp_m * 64 + mt * 16 + g;
        #pragma unroll
        for (int nt = 0; nt < 4; nt++) {
            int n = bn + warp_n * 32 + nt * 8 + tg2;
            *(float2*)&C[(size_t)m * N + n] =
                make_float2(acc[mt][nt][0], acc[mt][nt][1]);
            *(float2*)&C[(size_t)(m + 8) * N + n] =
                make_float2(acc[mt][nt][2], acc[mt][nt][3]);
        }
    }
}

// ---------------------------------------------------------------------------
// Flash attention: mma.sync split-bf16 + ldmatrix. Register-staged KV
// prefetch + double-buffered KV smem ring, ONE barrier per tile.
// CTA: 128 q-rows for one (b,h). 8 warps.
// ---------------------------------------------------------------------------
#define PADT_ 72
#define KVSTG_E_ (4 * 64 * PADT_)                    // elems per KV stage
#define KVSTG_B_ (KVSTG_E_ * 2)                      // 36864 bytes
#define ATT_SMEM_ ((2 * 128 * PADT_ + 2 * KVSTG_E_) * 2)   // 110592

__device__ __forceinline__ void kv_load(uint4 st[8], size_t base, size_t baseT,
                                        int k0, int tid) {
    #pragma unroll
    for (int u = 0; u < 8; u++) {
        int id = tid + (u << 8);
        int tile = id >> 9;      // 0:Kh 1:Kl 2:Vh 3:Vl
        int rem = id & 511;
        int row = rem >> 3;      // key row (K) / d row (V)
        int seg = rem & 7;
        const __nv_bfloat16* src;
        if (tile == 0)      src = g_kh + base + (size_t)(k0 + row) * DK_ + seg * 8;
        else if (tile == 1) src = g_kl + base + (size_t)(k0 + row) * DK_ + seg * 8;
        else if (tile == 2) src = g_vth + baseT + (size_t)row * S_ + k0 + seg * 8;
        else                src = g_vtl + baseT + (size_t)row * S_ + k0 + seg * 8;
        st[u] = *(const uint4*)src;
    }
}

__device__ __forceinline__ void kv_sts(__nv_bfloat16* sKV, const uint4 st[8],
                                       int stage, int tid) {
    __nv_bfloat16* dst = sKV + stage * KVSTG_E_;
    #pragma unroll
    for (int u = 0; u < 8; u++) {
        int id = tid + (u << 8);
        int tile = id >> 9;
        int rem = id & 511;
        int row = rem >> 3;
        int seg = rem & 7;
        *(uint4*)&dst[tile * 64 * PADT_ + row * PADT_ + seg * 8] = st[u];
    }
}

__global__ __launch_bounds__(256, 1)
void attn_mma() {
    extern __shared__ __nv_bfloat16 smb[];
    __nv_bfloat16* sQh = smb;
    __nv_bfloat16* sQl = sQh + 128 * PADT_;
    __nv_bfloat16* sKV = sQl + 128 * PADT_;   // 2 stages x (Kh,Kl,Vh,Vl)

    int tid = threadIdx.x;
    int lane = tid & 31, w = tid >> 5;
    int g = lane >> 2;
    int q2 = (lane & 3) << 1;
    int b = blockIdx.z, h = blockIdx.y;
    int qt = (int)gridDim.x - 1 - (int)blockIdx.x;   // heavy tiles first
    int q0 = qt << 7;
    size_t base = ((size_t)(b * H_ + h)) * S_ * DK_;
    size_t baseT = ((size_t)(b * H_ + h)) * DK_ * S_;

    int brow = (lane >> 4) * 8 + (lane & 7);
    int bcol = ((lane >> 3) & 1) * 8;
    uint32_t sKV_u = sm_u32(sKV);
    uint32_t bfrag = (brow * PADT_ + bcol) * 2;

    // ---- load Q tile (128 x 64) hi/lo into smem ----
    {
        int row = tid >> 1;
        int half = (tid & 1) << 2;
        const uint4* gh = (const uint4*)(g_qh + base + (size_t)(q0 + row) * DK_);
        const uint4* gl = (const uint4*)(g_ql + base + (size_t)(q0 + row) * DK_);
        uint4* dh = (uint4*)(sQh + row * PADT_);
        uint4* dl = (uint4*)(sQl + row * PADT_);
        #pragma unroll
        for (int u = 0; u < 4; u++) {
            dh[half + u] = gh[half + u];
            dl[half + u] = gl[half + u];
        }
    }

    // prefetch + store KV tile 0 into stage 0
    uint4 st[8];
    kv_load(st, base, baseT, 0, tid);
    kv_sts(sKV, st, 0, tid);
    __syncthreads();   // Q + KV stage 0 ready

    // ---- hoist Q fragments ----
    uint32_t qfh[4][4], qfl[4][4];
    {
        int arow = ((lane >> 3) & 1) * 8 + (lane & 7);
        int acol = (lane >> 4) * 8;
        uint32_t qh_u = sm_u32(sQh) + ((w * 16 + arow) * PADT_ + acol) * 2;
        uint32_t ql_u = sm_u32(sQl) + ((w * 16 + arow) * PADT_ + acol) * 2;
        #pragma unroll
        for (int ks = 0; ks < 4; ks++) {
            LDSM4(qfh[ks][0], qfh[ks][1], qfh[ks][2], qfh[ks][3],
                  qh_u + ks * 32);
            LDSM4(qfl[ks][0], qfl[ks][1], qfl[ks][2], qfl[ks][3],
                  ql_u + ks * 32);
        }
    }

    float oacc[8][4];
    #pragma unroll
    for (int nt = 0; nt < 8; nt++)
        #pragma unroll
        for (int r = 0; r < 4; r++) oacc[nt][r] = 0.f;
    float m0 = -1e30f, m1 = -1e30f, l0 = 0.f, l1 = 0.f;
    int row0 = q0 + w * 16 + g, row1 = row0 + 8;

    int nkt = 2 * (qt + 1);
    for (int kt = 0; kt < nkt; kt++) {
        int k0 = kt << 6;
        // prefetch next tile's LDGs (overlap this tile's compute)
        if (kt + 1 < nkt)
            kv_load(st, base, baseT, (kt + 1) << 6, tid);

        uint32_t stg = sKV_u + (kt & 1) * KVSTG_B_;
        uint32_t kA0  = stg + bfrag;
        uint32_t kA0l = kA0 + 64 * PADT_ * 2;
        uint32_t vA0  = kA0 + 2 * 64 * PADT_ * 2;
        uint32_t vA0l = kA0 + 3 * 64 * PADT_ * 2;

        // ---- S = Q K^T (3-term split) ----
        float sacc[8][4];
        #pragma unroll
        for (int nt = 0; nt < 8; nt++)
            #pragma unroll
            for (int r = 0; r < 4; r++) sacc[nt][r] = 0.f;

        #pragma unroll
        for (int ks = 0; ks < 4; ks++) {
            uint32_t kfh[8][2], kfl[8][2];
            #pragma unroll
            for (int p = 0; p < 4; p++) {
                uint32_t a = kA0 + (p * 16 * PADT_ + ks * 16) * 2;
                uint32_t al = kA0l + (p * 16 * PADT_ + ks * 16) * 2;
                LDSM4(kfh[2 * p][0], kfh[2 * p][1],
                      kfh[2 * p + 1][0], kfh[2 * p + 1][1], a);
                LDSM4(kfl[2 * p][0], kfl[2 * p][1],
                      kfl[2 * p + 1][0], kfl[2 * p + 1][1], al);
            }
            #pragma unroll
            for (int nt = 0; nt < 8; nt++) {
                MMA16816(sacc[nt], qfh[ks], kfh[nt]);
                MMA16816(sacc[nt], qfh[ks], kfl[nt]);
                MMA16816(sacc[nt], qfl[ks], kfh[nt]);
            }
        }

        // ---- scale + causal mask ----
        const float sc = 0.125f;
        if (k0 + 63 > row0) {
            #pragma unroll
            for (int nt = 0; nt < 8; nt++) {
                int c0 = k0 + nt * 8 + q2, c1 = c0 + 1;
                sacc[nt][0] = (c0 <= row0) ? sacc[nt][0] * sc : -1e30f;
                sacc[nt][1] = (c1 <= row0) ? sacc[nt][1] * sc : -1e30f;
                sacc[nt][2] = (c0 <= row1) ? sacc[nt][2] * sc : -1e30f;
                sacc[nt][3] = (c1 <= row1) ? sacc[nt][3] * sc : -1e30f;
            }
        } else {
            #pragma unroll
            for (int nt = 0; nt < 8; nt++)
                #pragma unroll
                for (int r = 0; r < 4; r++) sacc[nt][r] *= sc;
        }

        // ---- online softmax ----
        float rmax0 = -1e30f, rmax1 = -1e30f;
        #pragma unroll
        for (int nt = 0; nt < 8; nt++) {
            rmax0 = fmaxf(rmax0, fmaxf(sacc[nt][0], sacc[nt][1]));
            rmax1 = fmaxf(rmax1, fmaxf(sacc[nt][2], sacc[nt][3]));
        }
        rmax0 = fmaxf(rmax0, __shfl_xor_sync(0xffffffffu, rmax0, 1));
        rmax0 = fmaxf(rmax0, __shfl_xor_sync(0xffffffffu, rmax0, 2));
        rmax1 = fmaxf(rmax1, __shfl_xor_sync(0xffffffffu, rmax1, 1));
        rmax1 = fmaxf(rmax1, __shfl_xor_sync(0xffffffffu, rmax1, 2));
        float m0n = fmaxf(m0, rmax0), m1n = fmaxf(m1, rmax1);
        float corr0 = __expf(m0 - m0n), corr1 = __expf(m1 - m1n);
        float sum0 = 0.f, sum1 = 0.f;
        #pragma unroll
        for (int nt = 0; nt < 8; nt++) {
            sacc[nt][0] = __expf(sacc[nt][0] - m0n); sum0 += sacc[nt][0];
            sacc[nt][1] = __expf(sacc[nt][1] - m0n); sum0 += sacc[nt][1];
            sacc[nt][2] = __expf(sacc[nt][2] - m1n); sum1 += sacc[nt][2];
            sacc[nt][3] = __expf(sacc[nt][3] - m1n); sum1 += sacc[nt][3];
        }
        sum0 += __shfl_xor_sync(0xffffffffu, sum0, 1);
        sum0 += __shfl_xor_sync(0xffffffffu, sum0, 2);
        sum1 += __shfl_xor_sync(0xffffffffu, sum1, 1);
        sum1 += __shfl_xor_sync(0xffffffffu, sum1, 2);
        l0 = l0 * corr0 + sum0;  m0 = m0n;
        l1 = l1 * corr1 + sum1;  m1 = m1n;
        #pragma unroll
        for (int nt = 0; nt < 8; nt++) {
            oacc[nt][0] *= corr0; oacc[nt][1] *= corr0;
            oacc[nt][2] *= corr1; oacc[nt][3] *= corr1;
        }

        // ---- O += P V (P from registers; 3-term split) ----
        #pragma unroll
        for (int j = 0; j < 4; j++) {
            uint32_t ah[4], al[4];
            {
                float p0 = sacc[2 * j][0],     p1 = sacc[2 * j][1];
                float p2 = sacc[2 * j][2],     p3 = sacc[2 * j][3];
                float p4 = sacc[2 * j + 1][0], p5 = sacc[2 * j + 1][1];
                float p6 = sacc[2 * j + 1][2], p7 = sacc[2 * j + 1][3];
                ah[0] = pk2(p0, p1); ah[1] = pk2(p2, p3);
                ah[2] = pk2(p4, p5); ah[3] = pk2(p6, p7);
                al[0] = pk2(lo_of(p0), lo_of(p1)); al[1] = pk2(lo_of(p2), lo_of(p3));
                al[2] = pk2(lo_of(p4), lo_of(p5)); al[3] = pk2(lo_of(p6), lo_of(p7));
            }
            uint32_t vfh[8][2], vfl[8][2];
            #pragma unroll
            for (int p = 0; p < 4; p++) {
                uint32_t a = vA0 + (p * 16 * PADT_ + j * 16) * 2;
                uint32_t alo = vA0l + (p * 16 * PADT_ + j * 16) * 2;
                LDSM4(vfh[2 * p][0], vfh[2 * p][1],
                      vfh[2 * p + 1][0], vfh[2 * p + 1][1], a);
                LDSM4(vfl[2 * p][0], vfl[2 * p][1],
                      vfl[2 * p + 1][0], vfl[2 * p + 1][1], alo);
            }
            #pragma unroll
            for (int nt = 0; nt < 8; nt++) {
                MMA16816(oacc[nt], ah, vfh[nt]);
                MMA16816(oacc[nt], ah, vfl[nt]);
                MMA16816(oacc[nt], al, vfh[nt]);
            }
        }

        // store next tile into the other stage, then one barrier
        if (kt + 1 < nkt)
            kv_sts(sKV, st, (kt + 1) & 1, tid);
        __syncthreads();
    }

    // ---- epilogue ----
    float inv0 = 1.0f / l0, inv1 = 1.0f / l1;
    size_t ob0 = ((size_t)(b * S_ + row0)) * D_ + h * DK_;
    size_t ob1 = ((size_t)(b * S_ + row1)) * D_ + h * DK_;
    #pragma unroll
    for (int nt = 0; nt < 8; nt++) {
        int col = nt * 8 + q2;
        float e0 = oacc[nt][0] * inv0, e1 = oacc[nt][1] * inv0;
        float e2 = oacc[nt][2] * inv1, e3 = oacc[nt][3] * inv1;
        *(uint32_t*)&g_ath[ob0 + col] = pk2(e0, e1);
        *(uint32_t*)&g_atl[ob0 + col] = pk2(lo_of(e0), lo_of(e1));
        *(uint32_t*)&g_ath[ob1 + col] = pk2(e2, e3);
        *(uint32_t*)&g_atl[ob1 + col] = pk2(lo_of(e2), lo_of(e3));
    }
}

// ---------------------------------------------------------------------------
extern "C" void kernel_launch(void* const* d_in, const int* in_sizes, int n_in,
                              void* d_out, int out_size) {
    const float* x    = (const float*)d_in[0];
    const float* Wqkv = (const float*)d_in[1];
    const float* Wo   = (const float*)d_in[2];
    float* out = (float*)d_out;

    float* qkv_p;
    cudaGetSymbolAddress((void**)&qkv_p, g_qkv);
    __nv_bfloat16 *xh, *xl, *wqh, *wql, *woh, *wol, *ath, *atl;
    cudaGetSymbolAddress((void**)&xh, g_xh);
    cudaGetSymbolAddress((void**)&xl, g_xl);
    cudaGetSymbolAddress((void**)&wqh, g_wqh);
    cudaGetSymbolAddress((void**)&wql, g_wql);
    cudaGetSymbolAddress((void**)&woh, g_woh);
    cudaGetSymbolAddress((void**)&wol, g_wol);
    cudaGetSymbolAddress((void**)&ath, g_ath);
    cudaGetSymbolAddress((void**)&atl, g_atl);

    cudaFuncSetAttribute(attn_mma, cudaFuncAttributeMaxDynamicSharedMemorySize,
                         ATT_SMEM_);
    cudaFuncSetAttribute(gemm_mma, cudaFuncAttributeMaxDynamicSharedMemorySize,
                         GEMM_SMEM_);

    // 1. RoPE tables
    rope_table_k<<<(S_ * QUARTER_ + 255) / 256, 256>>>();
    // 2. split all three inputs in one launch
    split3_k<<<(N4_TOT_ + 255) / 256, 256>>>(x, Wqkv, Wo);
    // 3. QKV projection: [4096,1024] x [3072,1024]^T -> fp32
    gemm_mma<<<dim3(TD_ / 128, MROWS_ / 128), 256, GEMM_SMEM_>>>(
        xh, xl, wqh, wql, qkv_p, TD_);
    // 4. RoPE + split + relayout q,k; V transpose+split
    prep_k<<<(B_ * H_ * S_ * 8 + 255) / 256, 256>>>();
    vtrans_k<<<dim3(S_ / 64, H_, B_), 256>>>();
    // 5. causal flash attention (tensor cores) -> split bf16 [bs][D]
    attn_mma<<<dim3(S_ / 128, H_, B_), 256, ATT_SMEM_>>>();
    // 6. output projection -> d_out
    gemm_mma<<<dim3(D_ / 128, MROWS_ / 128), 256, GEMM_SMEM_>>>(
        ath, atl, woh, wol, out, D_);
}